// round 8
// baseline (speedup 1.0000x reference)
#include <cuda_runtime.h>
#include <cstdint>

// out[mu[k], e] += X1[m1[k], e] * X2[m2[k], e] * mult[k]
// M=9, K~100 runtime terms, ND = N*D = 2^20, fp32.
//
// R8 = R7 (256 thr, float2 col, 5 CTAs/SM, TMA-staged tiles, flat padded
// program) + X1-register-reuse: terms sorted by (mu,m1); 'a' register
// reloaded via predicated LDS only when m1 changes (flag = bit0 of packed
// offsets). Per term/warp crossbar: b 2wf + a ~1.1wf + prog 0.25 ~= 3.4 cyc.

#define M_CH    9
#define TILE    512                    // floats per channel per block
#define TILE_B  (TILE * 4)             // 2048 bytes per channel tile
#define THREADS 256
#define MAXK    128
#define PROGMAX 144

struct Smem {
    float2 sx[2 * M_CH * (TILE / 2)];  // 36864 B: X1 tiles then X2 tiles
    int2   prog[PROGMAX];              // {off1|flag | off2<<16, mult_bits}
    int    rawkey[MAXK];               // mu*9 + m1
    int    skey[MAXK];                 // sorted keys
    int    sm2[MAXK];                  // m2 per sorted rank
    int    smlt[MAXK];                 // mult bits per sorted rank
    int    seg[M_CH + 1];
    int    pseg[M_CH + 1];
    unsigned long long mbar;
};

__global__ void __launch_bounds__(THREADS, 5)
fused_kernel(const float* __restrict__ X1, const float* __restrict__ X2,
             const int* __restrict__ m1, const int* __restrict__ m2,
             const int* __restrict__ mu, const float* __restrict__ mult,
             float* __restrict__ out, int nd2, int K)
{
    __shared__ Smem s;
    const int t = threadIdx.x;
    const int base2 = blockIdx.x * (TILE / 2);
    const uint32_t mbar_addr = (uint32_t)__cvta_generic_to_shared(&s.mbar);

    // ---- phase 0: keys, mbarrier init -------------------------------------
    if (t < K) s.rawkey[t] = mu[t] * 9 + m1[t];
    if (t == 0) {
        asm volatile("mbarrier.init.shared.b64 [%0], %1;"
                     :: "r"(mbar_addr), "r"(1) : "memory");
        asm volatile("fence.proxy.async.shared::cta;" ::: "memory");
    }
    __syncthreads();

    // ---- phase 1: TMA issue (t0) + rank sort + mu histogram ---------------
    if (t == 0) {
        asm volatile("mbarrier.arrive.expect_tx.shared.b64 _, [%0], %1;"
                     :: "r"(mbar_addr), "r"((uint32_t)(2 * M_CH * TILE_B)) : "memory");
        uint32_t dst = (uint32_t)__cvta_generic_to_shared(&s.sx[0]);
        const char* src1 = (const char*)(X1 + (size_t)base2 * 2);
        const char* src2 = (const char*)(X2 + (size_t)base2 * 2);
        const size_t chanstride = (size_t)nd2 * 8;
#pragma unroll
        for (int m = 0; m < M_CH; m++) {
            asm volatile(
                "cp.async.bulk.shared::cta.global.mbarrier::complete_tx::bytes "
                "[%0], [%1], %2, [%3];"
                :: "r"(dst + m * TILE_B), "l"(src1 + m * chanstride),
                   "r"((uint32_t)TILE_B), "r"(mbar_addr) : "memory");
            asm volatile(
                "cp.async.bulk.shared::cta.global.mbarrier::complete_tx::bytes "
                "[%0], [%1], %2, [%3];"
                :: "r"(dst + (M_CH + m) * TILE_B), "l"(src2 + m * chanstride),
                   "r"((uint32_t)TILE_B), "r"(mbar_addr) : "memory");
        }
    }
    if (t < K) {
        const int mykey = s.rawkey[t];
        int r = 0;
        for (int j = 0; j < K; j++) {
            int kj = s.rawkey[j];
            r += (kj < mykey) | ((kj == mykey) & (j < t));
        }
        s.skey[r] = mykey;
        s.sm2[r]  = m2[t];
        s.smlt[r] = __float_as_int(mult[t]);
    }
    if (t <= M_CH) {                   // seg[m] = #{k : mu_k < m}
        int c = 0;
        for (int j = 0; j < K; j++) c += (s.rawkey[j] < t * 9);
        s.seg[t] = c;
    }
    __syncthreads();

    // ---- phase 2a: padded segment starts + inert pads (t0) ----------------
    if (t == 0) {
        int p = 0;
        for (int m = 0; m < M_CH; m++) {
            s.pseg[m] = p;
            int len  = s.seg[m + 1] - s.seg[m];
            int plen = (len + 1) & ~1;                 // pad to multiple of 2
            if (plen != len)
                s.prog[p + len] = make_int2(0, 0);     // no-reload, mult=0
            p += plen;
        }
        s.pseg[M_CH] = p;
    }
    __syncthreads();

    // ---- phase 2b: scatter sorted terms into padded program ---------------
    if (t < K) {
        const int key  = s.skey[t];
        const int m    = key / 9;
        const int m1i  = key - 9 * m;
        // reload iff m1 differs from previous sorted term (pads don't touch a)
        const int reload = (t == 0) || ((s.skey[t - 1] - 9 * (s.skey[t - 1] / 9)) != m1i);
        const int pos  = s.pseg[m] + (t - s.seg[m]);
        const int off1 = m1i * TILE_B | reload;                  // flag in bit0
        const int off2 = M_CH * TILE_B + s.sm2[t] * TILE_B;
        s.prog[pos] = make_int2(off1 | (off2 << 16), s.smlt[t]);
    }
    __syncthreads();

    // ---- wait for TMA -----------------------------------------------------
    asm volatile(
        "{\n\t.reg .pred P;\n\t"
        "W_%=:\n\t"
        "mbarrier.try_wait.parity.acquire.cta.shared::cta.b64 P, [%0], 0, 0x989680;\n\t"
        "@P bra.uni D_%=;\n\t"
        "bra.uni W_%=;\n\t"
        "D_%=:\n\t}"
        :: "r"(mbar_addr) : "memory");

    // ---- main loop: flat unroll-2, float2 col, register-cached 'a' --------
    const uint32_t colb = (uint32_t)__cvta_generic_to_shared(&s.sx[0]) + t * 8;
    float2* __restrict__ out2 = (float2*)out;
    unsigned long long a = 0ull;       // first real term always reloads
    int kptr = 0;

#pragma unroll
    for (int m = 0; m < M_CH; m++) {
        unsigned long long acc = 0ull;
        const int k1 = s.pseg[m + 1];
        for (int k = kptr; k < k1; k += 2) {
            int4 pr = *(const int4*)&s.prog[k];        // broadcast: 2 terms
#pragma unroll
            for (int u = 0; u < 2; u++) {
                const int pack = (u == 0) ? pr.x : pr.z;
                const int mlt  = (u == 0) ? pr.y : pr.w;
                unsigned long long b, c2;
                // predicated reload of 'a' (flag = bit0)
                asm("{\n\t.reg .pred p;\n\t"
                    ".reg .u32 ofs;\n\t"
                    "and.b32 ofs, %1, 0xFFFE;\n\t"
                    "setp.ne.u32 p, %1, ofs;\n\t"
                    "add.u32 ofs, ofs, %2;\n\t"
                    "@p ld.shared.b64 %0, [ofs];\n\t}"
                    : "+l"(a)
                    : "r"(pack & 0xFFFF), "r"(colb));
                asm("ld.shared.b64 %0, [%1];"
                    : "=l"(b) : "r"(colb + ((unsigned)pack >> 16)));
                asm("mov.b64 %0, {%1, %1};" : "=l"(c2) : "r"(mlt));
                asm("mul.rn.f32x2 %0, %1, %2;" : "=l"(b) : "l"(c2), "l"(b));
                asm("fma.rn.f32x2 %0, %1, %2, %3;"
                    : "=l"(acc) : "l"(a), "l"(b), "l"(acc));
            }
        }
        kptr = k1;
        *(unsigned long long*)&out2[(size_t)m * nd2 + base2 + t] = acc;
    }
}

extern "C" void kernel_launch(void* const* d_in, const int* in_sizes, int n_in,
                              void* d_out, int out_size)
{
    const float* X1   = (const float*)d_in[0];
    const float* X2   = (const float*)d_in[1];
    const int*   m1   = (const int*)d_in[2];
    const int*   m2   = (const int*)d_in[3];
    const int*   mu   = (const int*)d_in[4];
    const float* mult = (const float*)d_in[5];
    float*       out  = (float*)d_out;

    const int K   = in_sizes[2];
    const int ND  = in_sizes[0] / M_CH;    // N*D
    const int nd2 = ND / 2;

    fused_kernel<<<ND / TILE, THREADS>>>(X1, X2, m1, m2, mu, mult, out, nd2, K);
}

// round 9
// speedup vs baseline: 1.0743x; 1.0743x over previous
#include <cuda_runtime.h>
#include <cstdint>

// out[mu[k], e] += X1[m1[k], e] * X2[m2[k], e] * mult[k]
// M=9, K~100 runtime terms (mu pre-sorted), ND = N*D = 2^20, fp32.
//
// R9 = R7 (256 thr, float2 col/thread, 5 CTAs/SM, TMA-staged tiles, flat
// padded program, packed {off1|off2<<16, mult}) plus:
//   - software-pipelined prog broadcast (prefetch next int4 = 2 terms)
//   - dual accumulators to break the per-term FMA dependence chain.

#define M_CH    9
#define TILE    512                    // floats per channel per block
#define TILE_B  (TILE * 4)             // 2048 bytes per channel tile
#define THREADS 256
#define MAXK    128
#define PROGMAX 144                    // padded program + prefetch slack

struct Smem {
    float2 sx[2 * M_CH * (TILE / 2)];  // 36864 B: X1 tiles then X2 tiles
    int2   prog[PROGMAX];              // {off1 | off2<<16, mult_bits}
    int    rawmu[MAXK];
    int    seg[M_CH + 1];
    int    pseg[M_CH + 1];
    unsigned long long mbar;
};

__global__ void __launch_bounds__(THREADS, 5)
fused_kernel(const float* __restrict__ X1, const float* __restrict__ X2,
             const int* __restrict__ m1, const int* __restrict__ m2,
             const int* __restrict__ mu, const float* __restrict__ mult,
             float* __restrict__ out, int nd2, int K)
{
    __shared__ Smem s;
    const int t = threadIdx.x;
    const int base2 = blockIdx.x * (TILE / 2);
    const uint32_t mbar_addr = (uint32_t)__cvta_generic_to_shared(&s.mbar);

    // ---- phase 0: mu to smem, mbarrier init -------------------------------
    if (t < K) s.rawmu[t] = mu[t];
    if (t == 0) {
        asm volatile("mbarrier.init.shared.b64 [%0], %1;"
                     :: "r"(mbar_addr), "r"(1) : "memory");
        asm volatile("fence.proxy.async.shared::cta;" ::: "memory");
    }
    __syncthreads();

    // ---- phase 1: TMA issue (t0) + mu histogram ---------------------------
    if (t == 0) {
        asm volatile("mbarrier.arrive.expect_tx.shared.b64 _, [%0], %1;"
                     :: "r"(mbar_addr), "r"((uint32_t)(2 * M_CH * TILE_B)) : "memory");
        uint32_t dst = (uint32_t)__cvta_generic_to_shared(&s.sx[0]);
        const char* src1 = (const char*)(X1 + (size_t)base2 * 2);
        const char* src2 = (const char*)(X2 + (size_t)base2 * 2);
        const size_t chanstride = (size_t)nd2 * 8;
#pragma unroll
        for (int m = 0; m < M_CH; m++) {
            asm volatile(
                "cp.async.bulk.shared::cta.global.mbarrier::complete_tx::bytes "
                "[%0], [%1], %2, [%3];"
                :: "r"(dst + m * TILE_B), "l"(src1 + m * chanstride),
                   "r"((uint32_t)TILE_B), "r"(mbar_addr) : "memory");
            asm volatile(
                "cp.async.bulk.shared::cta.global.mbarrier::complete_tx::bytes "
                "[%0], [%1], %2, [%3];"
                :: "r"(dst + (M_CH + m) * TILE_B), "l"(src2 + m * chanstride),
                   "r"((uint32_t)TILE_B), "r"(mbar_addr) : "memory");
        }
    }
    if (t <= M_CH) {                   // seg[m] = #{k : mu_k < m}  (mu sorted)
        int c = 0;
        for (int j = 0; j < K; j++) c += (s.rawmu[j] < t);
        s.seg[t] = c;
    }
    __syncthreads();

    // ---- phase 2a: padded segment starts + inert pads (t0) ----------------
    if (t == 0) {
        int p = 0;
        for (int m = 0; m < M_CH; m++) {
            s.pseg[m] = p;
            int len  = s.seg[m + 1] - s.seg[m];
            int plen = (len + 1) & ~1;                 // pad to multiple of 2
            if (plen != len)
                s.prog[p + len] = make_int2(0, 0);     // mult = 0 dummy
            p += plen;
        }
        s.pseg[M_CH] = p;
    }
    __syncthreads();

    // ---- phase 2b: scatter real terms (input order; mu sorted) ------------
    if (t < K) {
        const int m   = s.rawmu[t];
        const int pos = s.pseg[m] + (t - s.seg[m]);
        const int off1 = m1[t] * TILE_B;
        const int off2 = m2[t] * TILE_B;               // bias folded into colb2
        s.prog[pos] = make_int2(off1 | (off2 << 16), __float_as_int(mult[t]));
    }
    __syncthreads();

    // ---- wait for TMA -----------------------------------------------------
    asm volatile(
        "{\n\t.reg .pred P;\n\t"
        "W_%=:\n\t"
        "mbarrier.try_wait.parity.acquire.cta.shared::cta.b64 P, [%0], 0, 0x989680;\n\t"
        "@P bra.uni D_%=;\n\t"
        "bra.uni W_%=;\n\t"
        "D_%=:\n\t}"
        :: "r"(mbar_addr) : "memory");

    // ---- main loop: flat unroll-2, pipelined prog, dual accumulators ------
    const uint32_t colb  = (uint32_t)__cvta_generic_to_shared(&s.sx[0]) + t * 8;
    const uint32_t colb2 = colb + M_CH * TILE_B;       // X2 region base
    float2* __restrict__ out2 = (float2*)out;
    int kptr = 0;

#pragma unroll
    for (int m = 0; m < M_CH; m++) {
        unsigned long long acc0 = 0ull, acc1 = 0ull;
        const int k1 = s.pseg[m + 1];
        int k = kptr;
        int4 pr = *(const int4*)&s.prog[k];            // prime the pipeline
        for (; k < k1; k += 2) {
            const int4 cur = pr;
            pr = *(const int4*)&s.prog[k + 2];         // prefetch (safe: padded)
            {
                unsigned long long a, b, c2;
                asm("ld.shared.b64 %0, [%1];"
                    : "=l"(a) : "r"(colb + (cur.x & 0xFFFF)));
                asm("ld.shared.b64 %0, [%1];"
                    : "=l"(b) : "r"(colb2 + ((unsigned)cur.x >> 16)));
                asm("mov.b64 %0, {%1, %1};" : "=l"(c2) : "r"(cur.y));
                asm("mul.rn.f32x2 %0, %1, %2;" : "=l"(b) : "l"(c2), "l"(b));
                asm("fma.rn.f32x2 %0, %1, %2, %3;"
                    : "=l"(acc0) : "l"(a), "l"(b), "l"(acc0));
            }
            {
                unsigned long long a, b, c2;
                asm("ld.shared.b64 %0, [%1];"
                    : "=l"(a) : "r"(colb + (cur.z & 0xFFFF)));
                asm("ld.shared.b64 %0, [%1];"
                    : "=l"(b) : "r"(colb2 + ((unsigned)cur.z >> 16)));
                asm("mov.b64 %0, {%1, %1};" : "=l"(c2) : "r"(cur.w));
                asm("mul.rn.f32x2 %0, %1, %2;" : "=l"(b) : "l"(c2), "l"(b));
                asm("fma.rn.f32x2 %0, %1, %2, %3;"
                    : "=l"(acc1) : "l"(a), "l"(b), "l"(acc1));
            }
        }
        kptr = k1;
        unsigned long long acc;
        asm("add.rn.f32x2 %0, %1, %2;" : "=l"(acc) : "l"(acc0), "l"(acc1));
        *(unsigned long long*)&out2[(size_t)m * nd2 + base2 + t] = acc;
    }
}

extern "C" void kernel_launch(void* const* d_in, const int* in_sizes, int n_in,
                              void* d_out, int out_size)
{
    const float* X1   = (const float*)d_in[0];
    const float* X2   = (const float*)d_in[1];
    const int*   m1   = (const int*)d_in[2];
    const int*   m2   = (const int*)d_in[3];
    const int*   mu   = (const int*)d_in[4];
    const float* mult = (const float*)d_in[5];
    float*       out  = (float*)d_out;

    const int K   = in_sizes[2];
    const int ND  = in_sizes[0] / M_CH;    // N*D
    const int nd2 = ND / 2;

    fused_kernel<<<ND / TILE, THREADS>>>(X1, X2, m1, m2, mu, mult, out, nd2, K);
}

// round 10
// speedup vs baseline: 1.1381x; 1.0594x over previous
#include <cuda_runtime.h>
#include <cstdint>

// out[mu[k], e] += X1[m1[k], e] * X2[m2[k], e] * mult[k]
// M=9, K~100 runtime terms (mu pre-sorted), ND = N*D = 2^20, fp32.
//
// R10: float4 column per thread (LDS.128 halves LDS instruction count — the
// MIO 2-cyc/SMSP issue floor was binding at float2), TILE=1024, 256 threads,
// dynamic smem ~75.5KB -> 3 CTAs/SM (24 warps). TMA-first setup: t0 issues
// 18 bulk copies immediately; warps 1-4 LDG term data into registers; warp 0
// builds seg/pseg with a shfl scan; 3 syncs total. Flat padded program
// {off1|off2<<16, mult}, unroll-2 with prog prefetch, dual accumulators.

#define M_CH    9
#define TILE    1024                   // floats per channel per block
#define TILE_B  (TILE * 4)             // 4096 bytes per channel tile
#define THREADS 256
#define MAXK    128
#define PROGMAX 144

struct Smem {
    float4 sx[2 * M_CH * (TILE / 4)];  // 73728 B: X1 tiles then X2 tiles
    int2   prog[PROGMAX];              // {off1 | off2<<16, mult_bits}
    int    rawmu[MAXK];
    int    seg[16];
    int    pseg[16];
    unsigned long long mbar;
};

__global__ void __launch_bounds__(THREADS, 3)
fused_kernel(const float* __restrict__ X1, const float* __restrict__ X2,
             const int* __restrict__ m1, const int* __restrict__ m2,
             const int* __restrict__ mu, const float* __restrict__ mult,
             float* __restrict__ out, int nd4, int K)
{
    extern __shared__ char smem_raw[];
    Smem* s = (Smem*)smem_raw;
    const int t = threadIdx.x;
    const int base4 = blockIdx.x * (TILE / 4);
    const uint32_t mbar_addr = (uint32_t)__cvta_generic_to_shared(&s->mbar);

    // ---- phase 0: t0 fires TMA immediately; warps 1-4 LDG term data -------
    if (t == 0) {
        asm volatile("mbarrier.init.shared.b64 [%0], %1;"
                     :: "r"(mbar_addr), "r"(1) : "memory");
        asm volatile("fence.proxy.async.shared::cta;" ::: "memory");
        asm volatile("mbarrier.arrive.expect_tx.shared.b64 _, [%0], %1;"
                     :: "r"(mbar_addr), "r"((uint32_t)(2 * M_CH * TILE_B)) : "memory");
        uint32_t dst = (uint32_t)__cvta_generic_to_shared(&s->sx[0]);
        const char* src1 = (const char*)(X1 + (size_t)base4 * 4);
        const char* src2 = (const char*)(X2 + (size_t)base4 * 4);
        const size_t chanstride = (size_t)nd4 * 16;
#pragma unroll
        for (int m = 0; m < M_CH; m++) {
            asm volatile(
                "cp.async.bulk.shared::cta.global.mbarrier::complete_tx::bytes "
                "[%0], [%1], %2, [%3];"
                :: "r"(dst + m * TILE_B), "l"(src1 + m * chanstride),
                   "r"((uint32_t)TILE_B), "r"(mbar_addr) : "memory");
            asm volatile(
                "cp.async.bulk.shared::cta.global.mbarrier::complete_tx::bytes "
                "[%0], [%1], %2, [%3];"
                :: "r"(dst + (M_CH + m) * TILE_B), "l"(src2 + m * chanstride),
                   "r"((uint32_t)TILE_B), "r"(mbar_addr) : "memory");
        }
    }

    // warps 1-4: one term per thread, straight from global into registers
    int myMu = 0, myPack = 0, myMult = 0;
    const int k_id = t - 32;
    const bool has_term = (k_id >= 0) && (k_id < K);
    if (has_term) {
        myMu   = mu[k_id];
        myPack = (m1[k_id] * TILE_B) | ((m2[k_id] * TILE_B) << 16);
        myMult = __float_as_int(mult[k_id]);
        s->rawmu[k_id] = myMu;
    }
    __syncthreads();                    // rawmu visible

    // ---- phase 1: warp 0 builds seg + pseg (shfl scan) + pad entries ------
    if (t < 16) {
        int segv = 0;
        if (t <= M_CH) {
            for (int j = 0; j < K; j++) segv += (s->rawmu[j] < t);
            s->seg[t] = segv;
        }
        const unsigned msk = 0xFFFFu;
        int segn = __shfl_down_sync(msk, segv, 1);
        int len  = segn - segv;                  // valid for lanes 0..8
        int plen = (len + 1) & ~1;
        int x = plen;                            // inclusive scan of plen
#pragma unroll
        for (int d = 1; d < 16; d <<= 1) {
            int y = __shfl_up_sync(msk, x, d);
            if (t >= d) x += y;
        }
        int psegv = x - plen;                    // exclusive scan
        if (t <= 8) {
            s->pseg[t] = psegv;
            if (len & 1)
                s->prog[psegv + len] = make_int2(0, 0);   // mult = 0 dummy
            if (t == 8) s->pseg[9] = psegv + plen;
        }
    }
    __syncthreads();                    // seg/pseg/pads visible

    // ---- phase 2: scatter real terms (input order; mu sorted) -------------
    if (has_term) {
        const int pos = s->pseg[myMu] + (k_id - s->seg[myMu]);
        s->prog[pos] = make_int2(myPack, myMult);
    }
    __syncthreads();

    // ---- wait for TMA -----------------------------------------------------
    asm volatile(
        "{\n\t.reg .pred P;\n\t"
        "W_%=:\n\t"
        "mbarrier.try_wait.parity.acquire.cta.shared::cta.b64 P, [%0], 0, 0x989680;\n\t"
        "@P bra.uni D_%=;\n\t"
        "bra.uni W_%=;\n\t"
        "D_%=:\n\t}"
        :: "r"(mbar_addr) : "memory");

    // ---- main loop: float4 column, unroll-2, prog prefetch, dual acc ------
    const uint32_t colb  = (uint32_t)__cvta_generic_to_shared(&s->sx[0]) + t * 16;
    const uint32_t colb2 = colb + M_CH * TILE_B;       // X2 region base
    float4* __restrict__ out4 = (float4*)out;
    int kptr = 0;

#pragma unroll
    for (int m = 0; m < M_CH; m++) {
        unsigned long long aL0 = 0ull, aH0 = 0ull;     // acc for even terms
        unsigned long long aL1 = 0ull, aH1 = 0ull;     // acc for odd terms
        const int k1 = s->pseg[m + 1];
        int k = kptr;
        int4 pr = *(const int4*)&s->prog[k];           // prime pipeline
        for (; k < k1; k += 2) {
            const int4 cur = pr;
            pr = *(const int4*)&s->prog[k + 2];        // prefetch (padded)
            {
                unsigned long long a0, a1, b0, b1, c2;
                asm("ld.shared.v2.u64 {%0, %1}, [%2];"
                    : "=l"(a0), "=l"(a1) : "r"(colb + (cur.x & 0xFFFF)));
                asm("ld.shared.v2.u64 {%0, %1}, [%2];"
                    : "=l"(b0), "=l"(b1) : "r"(colb2 + ((unsigned)cur.x >> 16)));
                asm("mov.b64 %0, {%1, %1};" : "=l"(c2) : "r"(cur.y));
                asm("mul.rn.f32x2 %0, %1, %2;" : "=l"(b0) : "l"(c2), "l"(b0));
                asm("mul.rn.f32x2 %0, %1, %2;" : "=l"(b1) : "l"(c2), "l"(b1));
                asm("fma.rn.f32x2 %0, %1, %2, %3;"
                    : "=l"(aL0) : "l"(a0), "l"(b0), "l"(aL0));
                asm("fma.rn.f32x2 %0, %1, %2, %3;"
                    : "=l"(aH0) : "l"(a1), "l"(b1), "l"(aH0));
            }
            {
                unsigned long long a0, a1, b0, b1, c2;
                asm("ld.shared.v2.u64 {%0, %1}, [%2];"
                    : "=l"(a0), "=l"(a1) : "r"(colb + (cur.z & 0xFFFF)));
                asm("ld.shared.v2.u64 {%0, %1}, [%2];"
                    : "=l"(b0), "=l"(b1) : "r"(colb2 + ((unsigned)cur.z >> 16)));
                asm("mov.b64 %0, {%1, %1};" : "=l"(c2) : "r"(cur.w));
                asm("mul.rn.f32x2 %0, %1, %2;" : "=l"(b0) : "l"(c2), "l"(b0));
                asm("mul.rn.f32x2 %0, %1, %2;" : "=l"(b1) : "l"(c2), "l"(b1));
                asm("fma.rn.f32x2 %0, %1, %2, %3;"
                    : "=l"(aL1) : "l"(a0), "l"(b0), "l"(aL1));
                asm("fma.rn.f32x2 %0, %1, %2, %3;"
                    : "=l"(aH1) : "l"(a1), "l"(b1), "l"(aH1));
            }
        }
        kptr = k1;
        ulonglong2 acc;
        asm("add.rn.f32x2 %0, %1, %2;" : "=l"(acc.x) : "l"(aL0), "l"(aL1));
        asm("add.rn.f32x2 %0, %1, %2;" : "=l"(acc.y) : "l"(aH0), "l"(aH1));
        *(ulonglong2*)&out4[(size_t)m * nd4 + base4 + t] = acc;   // STG.128
    }
}

extern "C" void kernel_launch(void* const* d_in, const int* in_sizes, int n_in,
                              void* d_out, int out_size)
{
    const float* X1   = (const float*)d_in[0];
    const float* X2   = (const float*)d_in[1];
    const int*   m1   = (const int*)d_in[2];
    const int*   m2   = (const int*)d_in[3];
    const int*   mu   = (const int*)d_in[4];
    const float* mult = (const float*)d_in[5];
    float*       out  = (float*)d_out;

    const int K   = in_sizes[2];
    const int ND  = in_sizes[0] / M_CH;    // N*D
    const int nd4 = ND / 4;

    const int smem = (int)sizeof(Smem);
    cudaFuncSetAttribute(fused_kernel,
                         cudaFuncAttributeMaxDynamicSharedMemorySize, smem);
    fused_kernel<<<ND / TILE, THREADS, smem>>>(X1, X2, m1, m2, mu, mult,
                                               out, nd4, K);
}